// round 1
// baseline (speedup 1.0000x reference)
#include <cuda_runtime.h>
#include <cstdint>

// ---------------------------------------------------------------------------
// GIN 2-layer: h = BN(relu((x + scatter_add(x)) @ W1 + b1)); out = BN(relu((h + scatter_add(h)) @ W2 + b2))
// N=50000, E=800000, F=H=128 (sizes derived from in_sizes at launch).
// ---------------------------------------------------------------------------

#define MAXN 50176   // rows of scratch (>= N, multiple of 64)

// Scratch (device globals; allocation-free).
__device__ float4 g_t4[(size_t)MAXN * 32];   // (x + agg) working buffer [N,128]
__device__ float4 g_h4[(size_t)MAXN * 32];   // relu(gemm) output       [N,128]
__device__ __align__(16) float g_sum[2][128];
__device__ __align__(16) float g_sq[2][128];
__device__ __align__(16) float g_sc[2][128];
__device__ __align__(16) float g_sh[2][128];
__device__ int g_idx64;

// ---------------------------------------------------------------------------
// Detect edge_index dtype (int64 vs int32) + zero BN stat accumulators.
// If data is int64 with values in [0, 2^31), every odd 32-bit word is 0.
// ---------------------------------------------------------------------------
__global__ void detect_zero_kernel(const int* __restrict__ w, int E) {
    __shared__ int any;
    if (threadIdx.x == 0) any = 0;
    __syncthreads();
    int limit = 2 * E; if (limit > 8192) limit = 8192;
    for (int i = 1 + 2 * (int)threadIdx.x; i < limit; i += 512)
        if (w[i] != 0) any = 1;
    __syncthreads();
    if (threadIdx.x == 0) g_idx64 = (any == 0) ? 1 : 0;
    if (threadIdx.x < 128) {
        g_sum[0][threadIdx.x] = 0.f; g_sum[1][threadIdx.x] = 0.f;
        g_sq[0][threadIdx.x]  = 0.f; g_sq[1][threadIdx.x]  = 0.f;
    }
}

// ---------------------------------------------------------------------------
// t = x  (init accumulator with self term)
// ---------------------------------------------------------------------------
__global__ void __launch_bounds__(256) init_t_kernel(const float4* __restrict__ x, int n4) {
    int i = blockIdx.x * 256 + threadIdx.x;
    if (i < n4) g_t4[i] = x[i];
}

// ---------------------------------------------------------------------------
// Edge scatter: one warp per edge; lane handles 4 contiguous features.
// APPLY=1: values are BN(layer0) of g_h on the fly (h*sc + sh).
// ---------------------------------------------------------------------------
template <int APPLY>
__global__ void __launch_bounds__(256) scatter_kernel(const float* __restrict__ x,
                                                      const void* __restrict__ eidx,
                                                      int E) {
    int gw   = (blockIdx.x * 256 + threadIdx.x) >> 5;
    int lane = threadIdx.x & 31;
    if (gw >= E) return;

    long long s, d;
    if (g_idx64) {
        const long long* p = (const long long*)eidx;
        s = p[gw]; d = p[(size_t)E + gw];
    } else {
        const int* p = (const int*)eidx;
        s = p[gw]; d = p[E + gw];
    }

    const float* vals = APPLY ? (const float*)g_h4 : x;
    float4 v = *(const float4*)(vals + (size_t)s * 128 + lane * 4);
    if (APPLY) {
        float4 a = *(const float4*)&g_sc[0][lane * 4];
        float4 b = *(const float4*)&g_sh[0][lane * 4];
        v.x = fmaf(v.x, a.x, b.x); v.y = fmaf(v.y, a.y, b.y);
        v.z = fmaf(v.z, a.z, b.z); v.w = fmaf(v.w, a.w, b.w);
    }
    float* o = (float*)g_t4 + (size_t)d * 128 + lane * 4;
    atomicAdd(o + 0, v.x); atomicAdd(o + 1, v.y);
    atomicAdd(o + 2, v.z); atomicAdd(o + 3, v.w);
}

// ---------------------------------------------------------------------------
// GEMM + bias + ReLU + per-column sum/sumsq partials (for BatchNorm).
// C[N,128] = A[N,128] @ W[128,128]; A = g_t, H = g_h.
// BM=64, BN=64, BK=32; 256 threads; per-thread 4x4 micro-tile.
// ---------------------------------------------------------------------------
#define BM 64
#define BN_ 64
#define BK 32

__global__ void __launch_bounds__(256) gemm_relu_stats_kernel(
        const float* __restrict__ W, const float* __restrict__ bias,
        int layer, int N) {
    __shared__ float As[BM][BK + 4];   // stride 36 floats (144B, 16B-aligned)
    __shared__ float Ws[BK][BN_ + 4];  // stride 68 floats (272B, 16B-aligned)
    __shared__ float s_sum[BN_];
    __shared__ float s_sq[BN_];

    const float* A = (const float*)g_t4;
    float* H = (float*)g_h4;

    int tid = threadIdx.x;
    int tx = tid & 15;          // col group: cols tx*4 .. tx*4+3
    int ty = tid >> 4;          // row group: rows ty*4 .. ty*4+3
    int row0 = blockIdx.x * BM;
    int col0 = blockIdx.y * BN_;

    float acc[4][4];
#pragma unroll
    for (int i = 0; i < 4; i++)
#pragma unroll
        for (int j = 0; j < 4; j++) acc[i][j] = 0.f;

    int lr = tid >> 3, lc = (tid & 7) * 4;      // A loader: 32 rows/pass
    int wr = tid >> 4, wc = (tid & 15) * 4;     // W loader: 16 rows/pass

    for (int k0 = 0; k0 < 128; k0 += BK) {
#pragma unroll
        for (int p = 0; p < 2; p++) {
            int r = lr + p * 32;
            int gr = row0 + r;
            float4 v = (gr < N) ? *(const float4*)(A + (size_t)gr * 128 + k0 + lc)
                                : make_float4(0.f, 0.f, 0.f, 0.f);
            *(float4*)&As[r][lc] = v;
        }
#pragma unroll
        for (int p = 0; p < 2; p++) {
            int r = wr + p * 16;
            float4 v = *(const float4*)(W + (size_t)(k0 + r) * 128 + col0 + wc);
            *(float4*)&Ws[r][wc] = v;
        }
        __syncthreads();

#pragma unroll
        for (int kk = 0; kk < BK; kk++) {
            float4 b = *(const float4*)&Ws[kk][tx * 4];
            float a0 = As[ty * 4 + 0][kk];
            float a1 = As[ty * 4 + 1][kk];
            float a2 = As[ty * 4 + 2][kk];
            float a3 = As[ty * 4 + 3][kk];
            acc[0][0] += a0 * b.x; acc[0][1] += a0 * b.y; acc[0][2] += a0 * b.z; acc[0][3] += a0 * b.w;
            acc[1][0] += a1 * b.x; acc[1][1] += a1 * b.y; acc[1][2] += a1 * b.z; acc[1][3] += a1 * b.w;
            acc[2][0] += a2 * b.x; acc[2][1] += a2 * b.y; acc[2][2] += a2 * b.z; acc[2][3] += a2 * b.w;
            acc[3][0] += a3 * b.x; acc[3][1] += a3 * b.y; acc[3][2] += a3 * b.z; acc[3][3] += a3 * b.w;
        }
        __syncthreads();
    }

    // Epilogue: bias + relu, store, accumulate column stats.
    float4 bv = *(const float4*)(bias + col0 + tx * 4);
    float psum[4] = {0.f, 0.f, 0.f, 0.f};
    float psq[4]  = {0.f, 0.f, 0.f, 0.f};

#pragma unroll
    for (int i = 0; i < 4; i++) {
        int gr = row0 + ty * 4 + i;
        float4 h;
        h.x = fmaxf(acc[i][0] + bv.x, 0.f);
        h.y = fmaxf(acc[i][1] + bv.y, 0.f);
        h.z = fmaxf(acc[i][2] + bv.z, 0.f);
        h.w = fmaxf(acc[i][3] + bv.w, 0.f);
        if (gr < N) {
            *(float4*)(H + (size_t)gr * 128 + col0 + tx * 4) = h;
            psum[0] += h.x; psum[1] += h.y; psum[2] += h.z; psum[3] += h.w;
            psq[0] += h.x * h.x; psq[1] += h.y * h.y;
            psq[2] += h.z * h.z; psq[3] += h.w * h.w;
        }
    }

    if (tid < BN_) { s_sum[tid] = 0.f; s_sq[tid] = 0.f; }
    __syncthreads();
    int cbase = tx * 4;
#pragma unroll
    for (int j = 0; j < 4; j++) {
        atomicAdd(&s_sum[cbase + j], psum[j]);
        atomicAdd(&s_sq[cbase + j], psq[j]);
    }
    __syncthreads();
    if (tid < BN_) {
        atomicAdd(&g_sum[layer][col0 + tid], s_sum[tid]);
        atomicAdd(&g_sq[layer][col0 + tid], s_sq[tid]);
    }
}

// ---------------------------------------------------------------------------
// BN finalize: per-column scale/shift from accumulated stats.
// ---------------------------------------------------------------------------
__global__ void bn_finalize_kernel(const float* __restrict__ gamma,
                                   const float* __restrict__ beta,
                                   int layer, float invN) {
    int c = threadIdx.x;  // 128 threads
    float m = g_sum[layer][c] * invN;
    float var = g_sq[layer][c] * invN - m * m;
    float s = gamma[c] * rsqrtf(var + 1e-5f);
    g_sc[layer][c] = s;
    g_sh[layer][c] = beta[c] - m * s;
}

// ---------------------------------------------------------------------------
// Apply BN elementwise: dst = g_h * sc[layer] + sh[layer].
// dst == nullptr -> write to g_t (layer-2 accumulator init).
// ---------------------------------------------------------------------------
__global__ void __launch_bounds__(256) bn_apply_kernel(float4* __restrict__ dst,
                                                       int layer, int n4) {
    int i = blockIdx.x * 256 + threadIdx.x;
    if (i >= n4) return;
    float4* out = dst ? dst : g_t4;
    int c = (i & 31) * 4;
    float4 v = g_h4[i];
    float4 a = *(const float4*)&g_sc[layer][c];
    float4 b = *(const float4*)&g_sh[layer][c];
    v.x = fmaf(v.x, a.x, b.x); v.y = fmaf(v.y, a.y, b.y);
    v.z = fmaf(v.z, a.z, b.z); v.w = fmaf(v.w, a.w, b.w);
    out[i] = v;
}

// ---------------------------------------------------------------------------
// Launch
// ---------------------------------------------------------------------------
extern "C" void kernel_launch(void* const* d_in, const int* in_sizes, int n_in,
                              void* d_out, int out_size) {
    const float* x    = (const float*)d_in[0];
    const void*  eidx = d_in[1];
    const float* W1   = (const float*)d_in[2];
    const float* b1   = (const float*)d_in[3];
    const float* W2   = (const float*)d_in[4];
    const float* b2   = (const float*)d_in[5];
    const float* g1   = (const float*)d_in[6];
    const float* be1  = (const float*)d_in[7];
    const float* g2   = (const float*)d_in[8];
    const float* be2  = (const float*)d_in[9];

    int N = in_sizes[0] / 128;
    int E = in_sizes[1] / 2;
    int n4 = N * 32;                      // float4 count
    int cgrid = (n4 + 255) / 256;
    int sgrid = (E + 7) / 8;              // 8 warps (edges) per block
    dim3 ggrid((N + BM - 1) / BM, 128 / BN_);
    float invN = 1.0f / (float)N;

    detect_zero_kernel<<<1, 256>>>((const int*)eidx, E);

    // ---- Layer 1 ----
    init_t_kernel<<<cgrid, 256>>>((const float4*)x, n4);
    scatter_kernel<0><<<sgrid, 256>>>(x, eidx, E);
    gemm_relu_stats_kernel<<<ggrid, 256>>>(W1, b1, 0, N);
    bn_finalize_kernel<<<1, 128>>>(g1, be1, 0, invN);

    // ---- Layer 2 (BN of layer-1 fused into init + scatter) ----
    bn_apply_kernel<<<cgrid, 256>>>(nullptr, 0, n4);          // t = BN(h1)
    scatter_kernel<1><<<sgrid, 256>>>(x, eidx, E);            // t += BN(h1)[src]
    gemm_relu_stats_kernel<<<ggrid, 256>>>(W2, b2, 1, N);
    bn_finalize_kernel<<<1, 128>>>(g2, be2, 1, invN);
    bn_apply_kernel<<<cgrid, 256>>>((float4*)d_out, 1, n4);   // out = BN(h2)
}

// round 2
// speedup vs baseline: 1.9809x; 1.9809x over previous
#include <cuda_runtime.h>
#include <cstdint>

// ---------------------------------------------------------------------------
// GIN 2-layer, CSR gather formulation (no float atomics):
//   build CSR(dst -> src) once; per layer: t[i] = f(i) + sum_{j in N(i)} f(j)
//   h = relu(t @ W + b); BN via fused per-column scale/shift.
// ---------------------------------------------------------------------------

#define MAXN 50176
#define MAXE 800000

__device__ float4 g_t4[(size_t)MAXN * 32];   // (x + agg) buffer [N,128]
__device__ float4 g_h4[(size_t)MAXN * 32];   // relu(gemm) out   [N,128]
__device__ __align__(16) float g_sum[2][128];
__device__ __align__(16) float g_sq[2][128];
__device__ __align__(16) float g_sc[2][128];
__device__ __align__(16) float g_sh[2][128];
__device__ int g_idx64;
__device__ int g_cnt[MAXN];
__device__ int g_rowptr[MAXN + 1];
__device__ int g_cursor[MAXN];
__device__ int g_adj[MAXE];

// ---------------------------------------------------------------------------
// Edge index accessors (int64 vs int32 decided at runtime).
// ---------------------------------------------------------------------------
__device__ __forceinline__ int edge_src(const void* eidx, int E, int e) {
    if (g_idx64) return (int)((const long long*)eidx)[e];
    return ((const int*)eidx)[e];
}
__device__ __forceinline__ int edge_dst(const void* eidx, int E, int e) {
    if (g_idx64) return (int)((const long long*)eidx)[(size_t)E + e];
    return ((const int*)eidx)[E + e];
}

// ---------------------------------------------------------------------------
// Detect dtype + zero BN accumulators.
// int64 with values < 2^31 => every odd 32-bit word is zero.
// ---------------------------------------------------------------------------
__global__ void detect_zero_kernel(const int* __restrict__ w, int E) {
    __shared__ int any;
    if (threadIdx.x == 0) any = 0;
    __syncthreads();
    int limit = 2 * E; if (limit > 8192) limit = 8192;
    for (int i = 1 + 2 * (int)threadIdx.x; i < limit; i += 512)
        if (w[i] != 0) any = 1;
    __syncthreads();
    if (threadIdx.x == 0) g_idx64 = (any == 0) ? 1 : 0;
    if (threadIdx.x < 128) {
        g_sum[0][threadIdx.x] = 0.f; g_sum[1][threadIdx.x] = 0.f;
        g_sq[0][threadIdx.x]  = 0.f; g_sq[1][threadIdx.x]  = 0.f;
    }
}

__global__ void zero_cnt_kernel(int N) {
    int i = blockIdx.x * 256 + threadIdx.x;
    if (i < N) g_cnt[i] = 0;
}

// ---------------------------------------------------------------------------
// CSR build: histogram -> exclusive scan -> fill.
// ---------------------------------------------------------------------------
__global__ void __launch_bounds__(256) hist_kernel(const void* __restrict__ eidx, int E) {
    int e = blockIdx.x * 256 + threadIdx.x;
    if (e < E) atomicAdd(&g_cnt[edge_dst(eidx, E, e)], 1);
}

__global__ void __launch_bounds__(1024) scan_kernel(int N) {
    __shared__ int part[1024];
    int tid = threadIdx.x;
    int per = (N + 1023) / 1024;
    int s = tid * per;
    int e = s + per; if (e > N) e = N;
    int sum = 0;
    for (int i = s; i < e; i++) sum += g_cnt[i];
    part[tid] = sum;
    __syncthreads();
    for (int off = 1; off < 1024; off <<= 1) {
        int v = 0;
        if (tid >= off) v = part[tid - off];
        __syncthreads();
        if (tid >= off) part[tid] += v;
        __syncthreads();
    }
    int run = (tid == 0) ? 0 : part[tid - 1];
    for (int i = s; i < e; i++) {
        int c = g_cnt[i];
        g_rowptr[i] = run;
        g_cursor[i] = run;
        run += c;
    }
    if (s < N && e == N) g_rowptr[N] = run;
}

__global__ void __launch_bounds__(256) fill_kernel(const void* __restrict__ eidx, int E) {
    int e = blockIdx.x * 256 + threadIdx.x;
    if (e >= E) return;
    int d = edge_dst(eidx, E, e);
    int s = edge_src(eidx, E, e);
    int pos = atomicAdd(&g_cursor[d], 1);
    g_adj[pos] = s;
}

// ---------------------------------------------------------------------------
// Gather aggregation: one warp per node, lane owns 4 features (float4).
//   APPLY=0: base = x;   acc = x[i]       + sum x[nb]
//   APPLY=1: base = g_h; acc = BN(h[i])   + sum BN(h[nb])   (BN fused via sc/sh[0])
// Writes g_t.
// ---------------------------------------------------------------------------
template <int APPLY>
__global__ void __launch_bounds__(256) aggregate_kernel(const float* __restrict__ x, int N) {
    int node = (blockIdx.x * 256 + threadIdx.x) >> 5;
    int lane = threadIdx.x & 31;
    if (node >= N) return;

    const float* base = APPLY ? (const float*)g_h4 : x;
    float4 sc, sh;
    if (APPLY) {
        sc = *(const float4*)&g_sc[0][lane * 4];
        sh = *(const float4*)&g_sh[0][lane * 4];
    }

    float4 v = *(const float4*)(base + (size_t)node * 128 + lane * 4);
    float4 acc;
    if (APPLY) {
        acc.x = fmaf(v.x, sc.x, sh.x); acc.y = fmaf(v.y, sc.y, sh.y);
        acc.z = fmaf(v.z, sc.z, sh.z); acc.w = fmaf(v.w, sc.w, sh.w);
    } else {
        acc = v;
    }

    int start = g_rowptr[node];
    int end   = g_rowptr[node + 1];
    for (int j0 = start; j0 < end; j0 += 32) {
        int n = end - j0; if (n > 32) n = 32;
        int myIdx = (lane < n) ? g_adj[j0 + lane] : 0;
#pragma unroll 4
        for (int k = 0; k < n; k++) {
            int nb = __shfl_sync(0xffffffffu, myIdx, k);
            float4 w = *(const float4*)(base + (size_t)nb * 128 + lane * 4);
            if (APPLY) {
                acc.x += fmaf(w.x, sc.x, sh.x); acc.y += fmaf(w.y, sc.y, sh.y);
                acc.z += fmaf(w.z, sc.z, sh.z); acc.w += fmaf(w.w, sc.w, sh.w);
            } else {
                acc.x += w.x; acc.y += w.y; acc.z += w.z; acc.w += w.w;
            }
        }
    }
    *(float4*)((float*)g_t4 + (size_t)node * 128 + lane * 4) = acc;
}

// ---------------------------------------------------------------------------
// GEMM + bias + ReLU + per-column sum/sumsq partials (BatchNorm stats).
// C[N,128] = g_t @ W; out -> g_h.  BM=64, BN=64, BK=32, 256 thr, 4x4 microtile.
// ---------------------------------------------------------------------------
#define BM 64
#define BN_ 64
#define BK 32

__global__ void __launch_bounds__(256) gemm_relu_stats_kernel(
        const float* __restrict__ W, const float* __restrict__ bias,
        int layer, int N) {
    __shared__ float As[BM][BK + 4];
    __shared__ float Ws[BK][BN_ + 4];
    __shared__ float s_sum[BN_];
    __shared__ float s_sq[BN_];

    const float* A = (const float*)g_t4;
    float* H = (float*)g_h4;

    int tid = threadIdx.x;
    int tx = tid & 15;
    int ty = tid >> 4;
    int row0 = blockIdx.x * BM;
    int col0 = blockIdx.y * BN_;

    float acc[4][4];
#pragma unroll
    for (int i = 0; i < 4; i++)
#pragma unroll
        for (int j = 0; j < 4; j++) acc[i][j] = 0.f;

    int lr = tid >> 3, lc = (tid & 7) * 4;
    int wr = tid >> 4, wc = (tid & 15) * 4;

    for (int k0 = 0; k0 < 128; k0 += BK) {
#pragma unroll
        for (int p = 0; p < 2; p++) {
            int r = lr + p * 32;
            int gr = row0 + r;
            float4 v = (gr < N) ? *(const float4*)(A + (size_t)gr * 128 + k0 + lc)
                                : make_float4(0.f, 0.f, 0.f, 0.f);
            *(float4*)&As[r][lc] = v;
        }
#pragma unroll
        for (int p = 0; p < 2; p++) {
            int r = wr + p * 16;
            float4 v = *(const float4*)(W + (size_t)(k0 + r) * 128 + col0 + wc);
            *(float4*)&Ws[r][wc] = v;
        }
        __syncthreads();

#pragma unroll
        for (int kk = 0; kk < BK; kk++) {
            float4 b = *(const float4*)&Ws[kk][tx * 4];
            float a0 = As[ty * 4 + 0][kk];
            float a1 = As[ty * 4 + 1][kk];
            float a2 = As[ty * 4 + 2][kk];
            float a3 = As[ty * 4 + 3][kk];
            acc[0][0] += a0 * b.x; acc[0][1] += a0 * b.y; acc[0][2] += a0 * b.z; acc[0][3] += a0 * b.w;
            acc[1][0] += a1 * b.x; acc[1][1] += a1 * b.y; acc[1][2] += a1 * b.z; acc[1][3] += a1 * b.w;
            acc[2][0] += a2 * b.x; acc[2][1] += a2 * b.y; acc[2][2] += a2 * b.z; acc[2][3] += a2 * b.w;
            acc[3][0] += a3 * b.x; acc[3][1] += a3 * b.y; acc[3][2] += a3 * b.z; acc[3][3] += a3 * b.w;
        }
        __syncthreads();
    }

    float4 bv = *(const float4*)(bias + col0 + tx * 4);
    float psum[4] = {0.f, 0.f, 0.f, 0.f};
    float psq[4]  = {0.f, 0.f, 0.f, 0.f};

#pragma unroll
    for (int i = 0; i < 4; i++) {
        int gr = row0 + ty * 4 + i;
        float4 h;
        h.x = fmaxf(acc[i][0] + bv.x, 0.f);
        h.y = fmaxf(acc[i][1] + bv.y, 0.f);
        h.z = fmaxf(acc[i][2] + bv.z, 0.f);
        h.w = fmaxf(acc[i][3] + bv.w, 0.f);
        if (gr < N) {
            *(float4*)(H + (size_t)gr * 128 + col0 + tx * 4) = h;
            psum[0] += h.x; psum[1] += h.y; psum[2] += h.z; psum[3] += h.w;
            psq[0] += h.x * h.x; psq[1] += h.y * h.y;
            psq[2] += h.z * h.z; psq[3] += h.w * h.w;
        }
    }

    if (tid < BN_) { s_sum[tid] = 0.f; s_sq[tid] = 0.f; }
    __syncthreads();
    int cbase = tx * 4;
#pragma unroll
    for (int j = 0; j < 4; j++) {
        atomicAdd(&s_sum[cbase + j], psum[j]);
        atomicAdd(&s_sq[cbase + j], psq[j]);
    }
    __syncthreads();
    if (tid < BN_) {
        atomicAdd(&g_sum[layer][col0 + tid], s_sum[tid]);
        atomicAdd(&g_sq[layer][col0 + tid], s_sq[tid]);
    }
}

// ---------------------------------------------------------------------------
// BN finalize: per-column scale/shift.
// ---------------------------------------------------------------------------
__global__ void bn_finalize_kernel(const float* __restrict__ gamma,
                                   const float* __restrict__ beta,
                                   int layer, float invN) {
    int c = threadIdx.x;
    float m = g_sum[layer][c] * invN;
    float var = g_sq[layer][c] * invN - m * m;
    float s = gamma[c] * rsqrtf(var + 1e-5f);
    g_sc[layer][c] = s;
    g_sh[layer][c] = beta[c] - m * s;
}

// ---------------------------------------------------------------------------
// out = g_h * sc[layer] + sh[layer]  (final output only)
// ---------------------------------------------------------------------------
__global__ void __launch_bounds__(256) bn_apply_kernel(float4* __restrict__ dst,
                                                       int layer, int n4) {
    int i = blockIdx.x * 256 + threadIdx.x;
    if (i >= n4) return;
    int c = (i & 31) * 4;
    float4 v = g_h4[i];
    float4 a = *(const float4*)&g_sc[layer][c];
    float4 b = *(const float4*)&g_sh[layer][c];
    v.x = fmaf(v.x, a.x, b.x); v.y = fmaf(v.y, a.y, b.y);
    v.z = fmaf(v.z, a.z, b.z); v.w = fmaf(v.w, a.w, b.w);
    dst[i] = v;
}

// ---------------------------------------------------------------------------
// Launch
// ---------------------------------------------------------------------------
extern "C" void kernel_launch(void* const* d_in, const int* in_sizes, int n_in,
                              void* d_out, int out_size) {
    const float* x    = (const float*)d_in[0];
    const void*  eidx = d_in[1];
    const float* W1   = (const float*)d_in[2];
    const float* b1   = (const float*)d_in[3];
    const float* W2   = (const float*)d_in[4];
    const float* b2   = (const float*)d_in[5];
    const float* g1   = (const float*)d_in[6];
    const float* be1  = (const float*)d_in[7];
    const float* g2   = (const float*)d_in[8];
    const float* be2  = (const float*)d_in[9];

    int N = in_sizes[0] / 128;
    int E = in_sizes[1] / 2;
    int n4 = N * 32;
    int cgrid = (n4 + 255) / 256;
    int egrid = (E + 255) / 256;
    int ngrid = (N + 255) / 256;
    int agrid = (N * 32 + 255) / 256;          // warp per node, 8 nodes/block
    dim3 ggrid((N + BM - 1) / BM, 128 / BN_);
    float invN = 1.0f / (float)N;

    // ---- CSR build (once, serves both layers) ----
    detect_zero_kernel<<<1, 256>>>((const int*)eidx, E);
    zero_cnt_kernel<<<ngrid, 256>>>(N);
    hist_kernel<<<egrid, 256>>>(eidx, E);
    scan_kernel<<<1, 1024>>>(N);
    fill_kernel<<<egrid, 256>>>(eidx, E);

    // ---- Layer 1 ----
    aggregate_kernel<0><<<agrid, 256>>>(x, N);
    gemm_relu_stats_kernel<<<ggrid, 256>>>(W1, b1, 0, N);
    bn_finalize_kernel<<<1, 128>>>(g1, be1, 0, invN);

    // ---- Layer 2 (BN of layer 1 fused into the gather) ----
    aggregate_kernel<1><<<agrid, 256>>>(x, N);
    gemm_relu_stats_kernel<<<ggrid, 256>>>(W2, b2, 1, N);
    bn_finalize_kernel<<<1, 128>>>(g2, be2, 1, invN);
    bn_apply_kernel<<<cgrid, 256>>>((float4*)d_out, 1, n4);
}

// round 3
// speedup vs baseline: 2.6602x; 1.3429x over previous
#include <cuda_runtime.h>
#include <cstdint>

typedef unsigned long long u64;

#define MAXN 50176
#define MAXE 800000

__device__ float4 g_t4[(size_t)MAXN * 32];   // (x + agg) buffer [N,128]
__device__ float4 g_h4[(size_t)MAXN * 32];   // relu(gemm) out   [N,128]
__device__ __align__(16) float g_sum[2][128];
__device__ __align__(16) float g_sq[2][128];
__device__ __align__(16) float g_sc[2][128];
__device__ __align__(16) float g_sh[2][128];
__device__ int g_idx64;
__device__ int g_cnt[MAXN];
__device__ int g_rowptr[MAXN + 1];
__device__ int g_cursor[MAXN];
__device__ int g_adj[MAXE];
__device__ int g_bsum[256];

// ---------------------------------------------------------------------------
// Edge index accessors (int64 vs int32 decided at runtime).
// ---------------------------------------------------------------------------
__device__ __forceinline__ int edge_src(const void* eidx, int E, int e) {
    if (g_idx64) return (int)((const long long*)eidx)[e];
    return ((const int*)eidx)[e];
}
__device__ __forceinline__ int edge_dst(const void* eidx, int E, int e) {
    if (g_idx64) return (int)((const long long*)eidx)[(size_t)E + e];
    return ((const int*)eidx)[E + e];
}

// ---------------------------------------------------------------------------
// Detect dtype + zero BN accumulators + zero counts.
// ---------------------------------------------------------------------------
__global__ void detect_zero_kernel(const int* __restrict__ w, int E) {
    __shared__ int any;
    if (threadIdx.x == 0) any = 0;
    __syncthreads();
    int limit = 2 * E; if (limit > 8192) limit = 8192;
    for (int i = 1 + 2 * (int)threadIdx.x; i < limit; i += 512)
        if (w[i] != 0) any = 1;
    __syncthreads();
    if (threadIdx.x == 0) g_idx64 = (any == 0) ? 1 : 0;
    if (threadIdx.x < 128) {
        g_sum[0][threadIdx.x] = 0.f; g_sum[1][threadIdx.x] = 0.f;
        g_sq[0][threadIdx.x]  = 0.f; g_sq[1][threadIdx.x]  = 0.f;
    }
}

__global__ void zero_cnt_kernel(int N) {
    int i = blockIdx.x * 256 + threadIdx.x;
    if (i < N) g_cnt[i] = 0;
}

__global__ void __launch_bounds__(256) hist_kernel(const void* __restrict__ eidx, int E) {
    int e = blockIdx.x * 256 + threadIdx.x;
    if (e < E) atomicAdd(&g_cnt[edge_dst(eidx, E, e)], 1);
}

// ---------------------------------------------------------------------------
// 3-phase grid-wide exclusive scan of g_cnt[0..N) into g_rowptr[0..N].
// Phase 1: per-block (1024 elems) local exclusive scan + block total.
// Phase 2: single-block scan of <=256 block totals.
// Phase 3: add block offsets; also init g_cursor.
// ---------------------------------------------------------------------------
#define SCAN_T 256
#define SCAN_E 4
#define SCAN_B (SCAN_T * SCAN_E)   // 1024 per block

__global__ void __launch_bounds__(SCAN_T) scan1_kernel(int N) {
    __shared__ int sh[SCAN_T];
    int b = blockIdx.x, t = threadIdx.x;
    int base = b * SCAN_B + t * SCAN_E;
    int v[SCAN_E];
    int s = 0;
#pragma unroll
    for (int i = 0; i < SCAN_E; i++) {
        v[i] = (base + i < N) ? g_cnt[base + i] : 0;
        s += v[i];
    }
    sh[t] = s;
    __syncthreads();
    for (int off = 1; off < SCAN_T; off <<= 1) {
        int u = 0;
        if (t >= off) u = sh[t - off];
        __syncthreads();
        if (t >= off) sh[t] += u;
        __syncthreads();
    }
    int run = (t == 0) ? 0 : sh[t - 1];
#pragma unroll
    for (int i = 0; i < SCAN_E; i++) {
        if (base + i <= N) g_rowptr[base + i] = run;   // local exclusive
        run += v[i];
    }
    if (t == SCAN_T - 1) g_bsum[b] = sh[SCAN_T - 1];
}

__global__ void __launch_bounds__(SCAN_T) scan2_kernel(int nb) {
    __shared__ int sh[SCAN_T];
    int t = threadIdx.x;
    sh[t] = (t < nb) ? g_bsum[t] : 0;
    __syncthreads();
    for (int off = 1; off < SCAN_T; off <<= 1) {
        int u = 0;
        if (t >= off) u = sh[t - off];
        __syncthreads();
        if (t >= off) sh[t] += u;
        __syncthreads();
    }
    if (t < nb) g_bsum[t] = (t == 0) ? 0 : sh[t - 1];  // exclusive
}

__global__ void __launch_bounds__(256) scan3_kernel(int N) {
    int i = blockIdx.x * 256 + threadIdx.x;
    if (i > N) return;
    int v = g_rowptr[i] + g_bsum[i / SCAN_B];
    g_rowptr[i] = v;
    if (i < N) g_cursor[i] = v;
}

__global__ void __launch_bounds__(256) fill_kernel(const void* __restrict__ eidx, int E) {
    int e = blockIdx.x * 256 + threadIdx.x;
    if (e >= E) return;
    int d = edge_dst(eidx, E, e);
    int s = edge_src(eidx, E, e);
    int pos = atomicAdd(&g_cursor[d], 1);
    g_adj[pos] = s;
}

// ---------------------------------------------------------------------------
// Gather aggregation: one warp per node, lane owns 4 features (float4).
// APPLY=1 fuses BN(layer0) scale/shift into the gathered values.
// ---------------------------------------------------------------------------
template <int APPLY>
__global__ void __launch_bounds__(256) aggregate_kernel(const float* __restrict__ x, int N) {
    int node = (blockIdx.x * 256 + threadIdx.x) >> 5;
    int lane = threadIdx.x & 31;
    if (node >= N) return;

    const float* base = APPLY ? (const float*)g_h4 : x;
    float4 sc, sh;
    if (APPLY) {
        sc = *(const float4*)&g_sc[0][lane * 4];
        sh = *(const float4*)&g_sh[0][lane * 4];
    }

    float4 v = *(const float4*)(base + (size_t)node * 128 + lane * 4);
    float4 acc;
    if (APPLY) {
        acc.x = fmaf(v.x, sc.x, sh.x); acc.y = fmaf(v.y, sc.y, sh.y);
        acc.z = fmaf(v.z, sc.z, sh.z); acc.w = fmaf(v.w, sc.w, sh.w);
    } else {
        acc = v;
    }

    int start = g_rowptr[node];
    int end   = g_rowptr[node + 1];
    for (int j0 = start; j0 < end; j0 += 32) {
        int n = end - j0; if (n > 32) n = 32;
        int myIdx = (lane < n) ? g_adj[j0 + lane] : 0;
#pragma unroll 4
        for (int k = 0; k < n; k++) {
            int nb = __shfl_sync(0xffffffffu, myIdx, k);
            float4 w = *(const float4*)(base + (size_t)nb * 128 + lane * 4);
            if (APPLY) {
                acc.x += fmaf(w.x, sc.x, sh.x); acc.y += fmaf(w.y, sc.y, sh.y);
                acc.z += fmaf(w.z, sc.z, sh.z); acc.w += fmaf(w.w, sc.w, sh.w);
            } else {
                acc.x += w.x; acc.y += w.y; acc.z += w.z; acc.w += w.w;
            }
        }
    }
    *(float4*)((float*)g_t4 + (size_t)node * 128 + lane * 4) = acc;
}

// ---------------------------------------------------------------------------
// Packed-f32x2 helpers (Blackwell FFMA2 — PTX-only path).
// ---------------------------------------------------------------------------
__device__ __forceinline__ void fma2(u64& d, u64 a, u64 b) {
    asm("fma.rn.f32x2 %0, %1, %2, %0;" : "+l"(d) : "l"(a), "l"(b));
}
__device__ __forceinline__ u64 pack2(float a) {
    u64 r;
    asm("mov.b64 %0, {%1, %1};" : "=l"(r) : "f"(a));
    return r;
}
__device__ __forceinline__ float2 unpack2(u64 v) {
    float lo, hi;
    asm("mov.b64 {%0, %1}, %2;" : "=f"(lo), "=f"(hi) : "l"(v));
    return make_float2(lo, hi);
}

// ---------------------------------------------------------------------------
// GEMM + bias + ReLU + BN stat partials; f32x2 packed accumulation.
// C[N,128] = g_t @ W -> g_h.  BM=64, BN=64, BK=32, 256 thr, 4x4 microtile.
// ---------------------------------------------------------------------------
#define BM 64
#define BN_ 64
#define BK 32

__global__ void __launch_bounds__(256) gemm_relu_stats_kernel(
        const float* __restrict__ W, const float* __restrict__ bias,
        int layer, int N) {
    __shared__ float As[BM][BK + 4];    // 36-float stride (16B-aligned rows)
    __shared__ float Ws[BK][BN_ + 4];   // 68-float stride (16B-aligned rows)
    __shared__ float s_sum[BN_];
    __shared__ float s_sq[BN_];

    const float* A = (const float*)g_t4;
    float* H = (float*)g_h4;

    int tid = threadIdx.x;
    int tx = tid & 15;          // 4 cols: tx*4..tx*4+3
    int ty = tid >> 4;          // 4 rows: ty*4..ty*4+3
    int row0 = blockIdx.x * BM;
    int col0 = blockIdx.y * BN_;

    u64 acc2[4][2];
#pragma unroll
    for (int i = 0; i < 4; i++) { acc2[i][0] = 0ull; acc2[i][1] = 0ull; }

    int lr = tid >> 3, lc = (tid & 7) * 4;
    int wr = tid >> 4, wc = (tid & 15) * 4;

    for (int k0 = 0; k0 < 128; k0 += BK) {
#pragma unroll
        for (int p = 0; p < 2; p++) {
            int r = lr + p * 32;
            int gr = row0 + r;
            float4 v = (gr < N) ? *(const float4*)(A + (size_t)gr * 128 + k0 + lc)
                                : make_float4(0.f, 0.f, 0.f, 0.f);
            *(float4*)&As[r][lc] = v;
        }
#pragma unroll
        for (int p = 0; p < 2; p++) {
            int r = wr + p * 16;
            float4 v = *(const float4*)(W + (size_t)(k0 + r) * 128 + col0 + wc);
            *(float4*)&Ws[r][wc] = v;
        }
        __syncthreads();

#pragma unroll
        for (int kk = 0; kk < BK; kk++) {
            u64 b01 = *(const u64*)&Ws[kk][tx * 4];
            u64 b23 = *(const u64*)&Ws[kk][tx * 4 + 2];
            u64 a0 = pack2(As[ty * 4 + 0][kk]);
            u64 a1 = pack2(As[ty * 4 + 1][kk]);
            u64 a2 = pack2(As[ty * 4 + 2][kk]);
            u64 a3 = pack2(As[ty * 4 + 3][kk]);
            fma2(acc2[0][0], a0, b01); fma2(acc2[0][1], a0, b23);
            fma2(acc2[1][0], a1, b01); fma2(acc2[1][1], a1, b23);
            fma2(acc2[2][0], a2, b01); fma2(acc2[2][1], a2, b23);
            fma2(acc2[3][0], a3, b01); fma2(acc2[3][1], a3, b23);
        }
        __syncthreads();
    }

    float4 bv = *(const float4*)(bias + col0 + tx * 4);
    float psum[4] = {0.f, 0.f, 0.f, 0.f};
    float psq[4]  = {0.f, 0.f, 0.f, 0.f};

#pragma unroll
    for (int i = 0; i < 4; i++) {
        int gr = row0 + ty * 4 + i;
        float2 p01 = unpack2(acc2[i][0]);
        float2 p23 = unpack2(acc2[i][1]);
        float4 h;
        h.x = fmaxf(p01.x + bv.x, 0.f);
        h.y = fmaxf(p01.y + bv.y, 0.f);
        h.z = fmaxf(p23.x + bv.z, 0.f);
        h.w = fmaxf(p23.y + bv.w, 0.f);
        if (gr < N) {
            *(float4*)(H + (size_t)gr * 128 + col0 + tx * 4) = h;
            psum[0] += h.x; psum[1] += h.y; psum[2] += h.z; psum[3] += h.w;
            psq[0] += h.x * h.x; psq[1] += h.y * h.y;
            psq[2] += h.z * h.z; psq[3] += h.w * h.w;
        }
    }

    if (tid < BN_) { s_sum[tid] = 0.f; s_sq[tid] = 0.f; }
    __syncthreads();
    int cbase = tx * 4;
#pragma unroll
    for (int j = 0; j < 4; j++) {
        atomicAdd(&s_sum[cbase + j], psum[j]);
        atomicAdd(&s_sq[cbase + j], psq[j]);
    }
    __syncthreads();
    if (tid < BN_) {
        atomicAdd(&g_sum[layer][col0 + tid], s_sum[tid]);
        atomicAdd(&g_sq[layer][col0 + tid], s_sq[tid]);
    }
}

// ---------------------------------------------------------------------------
// BN finalize + final apply.
// ---------------------------------------------------------------------------
__global__ void bn_finalize_kernel(const float* __restrict__ gamma,
                                   const float* __restrict__ beta,
                                   int layer, float invN) {
    int c = threadIdx.x;
    float m = g_sum[layer][c] * invN;
    float var = g_sq[layer][c] * invN - m * m;
    float s = gamma[c] * rsqrtf(var + 1e-5f);
    g_sc[layer][c] = s;
    g_sh[layer][c] = beta[c] - m * s;
}

__global__ void __launch_bounds__(256) bn_apply_kernel(float4* __restrict__ dst,
                                                       int layer, int n4) {
    int i = blockIdx.x * 256 + threadIdx.x;
    if (i >= n4) return;
    int c = (i & 31) * 4;
    float4 v = g_h4[i];
    float4 a = *(const float4*)&g_sc[layer][c];
    float4 b = *(const float4*)&g_sh[layer][c];
    v.x = fmaf(v.x, a.x, b.x); v.y = fmaf(v.y, a.y, b.y);
    v.z = fmaf(v.z, a.z, b.z); v.w = fmaf(v.w, a.w, b.w);
    dst[i] = v;
}

// ---------------------------------------------------------------------------
// Launch
// ---------------------------------------------------------------------------
extern "C" void kernel_launch(void* const* d_in, const int* in_sizes, int n_in,
                              void* d_out, int out_size) {
    const float* x    = (const float*)d_in[0];
    const void*  eidx = d_in[1];
    const float* W1   = (const float*)d_in[2];
    const float* b1   = (const float*)d_in[3];
    const float* W2   = (const float*)d_in[4];
    const float* b2   = (const float*)d_in[5];
    const float* g1   = (const float*)d_in[6];
    const float* be1  = (const float*)d_in[7];
    const float* g2   = (const float*)d_in[8];
    const float* be2  = (const float*)d_in[9];

    int N = in_sizes[0] / 128;
    int E = in_sizes[1] / 2;
    int n4 = N * 32;
    int cgrid = (n4 + 255) / 256;
    int egrid = (E + 255) / 256;
    int ngrid = (N + 255) / 256;
    int agrid = (N * 32 + 255) / 256;
    int nb = (N + SCAN_B) / SCAN_B + ((N + 1) % SCAN_B ? 1 : 0);
    nb = (N + 1 + SCAN_B - 1) / SCAN_B;
    dim3 ggrid((N + BM - 1) / BM, 128 / BN_);
    float invN = 1.0f / (float)N;

    // ---- CSR build ----
    detect_zero_kernel<<<1, 256>>>((const int*)eidx, E);
    zero_cnt_kernel<<<ngrid, 256>>>(N);
    hist_kernel<<<egrid, 256>>>(eidx, E);
    scan1_kernel<<<nb, SCAN_T>>>(N);
    scan2_kernel<<<1, SCAN_T>>>(nb);
    scan3_kernel<<<(N + 256) / 256, 256>>>(N);
    fill_kernel<<<egrid, 256>>>(eidx, E);

    // ---- Layer 1 ----
    aggregate_kernel<0><<<agrid, 256>>>(x, N);
    gemm_relu_stats_kernel<<<ggrid, 256>>>(W1, b1, 0, N);
    bn_finalize_kernel<<<1, 128>>>(g1, be1, 0, invN);

    // ---- Layer 2 (BN of layer 1 fused into the gather) ----
    aggregate_kernel<1><<<agrid, 256>>>(x, N);
    gemm_relu_stats_kernel<<<ggrid, 256>>>(W2, b2, 1, N);
    bn_finalize_kernel<<<1, 128>>>(g2, be2, 1, invN);
    bn_apply_kernel<<<cgrid, 256>>>((float4*)d_out, 1, n4);
}

// round 5
// speedup vs baseline: 2.9652x; 1.1146x over previous
#include <cuda_runtime.h>
#include <cuda_bf16.h>
#include <cstdint>

typedef unsigned long long u64;
typedef uint32_t u32;

#define MAXN 50176
#define MAXE 800000

__device__ float4 g_t4[(size_t)MAXN * 32];   // (x + agg) buffer [N,128]
__device__ float4 g_h4[(size_t)MAXN * 32];   // relu(gemm) out   [N,128]
__device__ __align__(16) float g_sum[2][128];
__device__ __align__(16) float g_sq[2][128];
__device__ __align__(16) float g_sc[2][128];
__device__ __align__(16) float g_sh[2][128];
__device__ int g_idx64;
__device__ int g_cnt[MAXN];
__device__ int g_rowptr[MAXN + 1];
__device__ int g_cursor[MAXN];
__device__ int g_adj[MAXE];
__device__ int g_bsum[256];
// W fragments (mma B-operand layout), split hi/lo bf16 pairs, per layer.
__device__ __align__(16) u32 g_wf_hi[2][8192];
__device__ __align__(16) u32 g_wf_lo[2][8192];

// ===========================================================================
// Edge index accessors + CSR build
// ===========================================================================
__device__ __forceinline__ int edge_src(const void* eidx, int E, int e) {
    if (g_idx64) return (int)((const long long*)eidx)[e];
    return ((const int*)eidx)[e];
}
__device__ __forceinline__ int edge_dst(const void* eidx, int E, int e) {
    if (g_idx64) return (int)((const long long*)eidx)[(size_t)E + e];
    return ((const int*)eidx)[E + e];
}

__global__ void detect_zero_kernel(const int* __restrict__ w, int E) {
    __shared__ int any;
    if (threadIdx.x == 0) any = 0;
    __syncthreads();
    int limit = 2 * E; if (limit > 8192) limit = 8192;
    for (int i = 1 + 2 * (int)threadIdx.x; i < limit; i += 512)
        if (w[i] != 0) any = 1;
    __syncthreads();
    if (threadIdx.x == 0) g_idx64 = (any == 0) ? 1 : 0;
    if (threadIdx.x < 128) {
        g_sum[0][threadIdx.x] = 0.f; g_sum[1][threadIdx.x] = 0.f;
        g_sq[0][threadIdx.x]  = 0.f; g_sq[1][threadIdx.x]  = 0.f;
    }
}

__global__ void zero_cnt_kernel(int N) {
    int i = blockIdx.x * 256 + threadIdx.x;
    if (i < N) g_cnt[i] = 0;
}

__global__ void __launch_bounds__(256) hist_kernel(const void* __restrict__ eidx, int E) {
    int e = blockIdx.x * 256 + threadIdx.x;
    if (e < E) atomicAdd(&g_cnt[edge_dst(eidx, E, e)], 1);
}

#define SCAN_T 256
#define SCAN_E 4
#define SCAN_B (SCAN_T * SCAN_E)

__global__ void __launch_bounds__(SCAN_T) scan1_kernel(int N) {
    __shared__ int sh[SCAN_T];
    int b = blockIdx.x, t = threadIdx.x;
    int base = b * SCAN_B + t * SCAN_E;
    int v[SCAN_E];
    int s = 0;
#pragma unroll
    for (int i = 0; i < SCAN_E; i++) {
        v[i] = (base + i < N) ? g_cnt[base + i] : 0;
        s += v[i];
    }
    sh[t] = s;
    __syncthreads();
    for (int off = 1; off < SCAN_T; off <<= 1) {
        int u = 0;
        if (t >= off) u = sh[t - off];
        __syncthreads();
        if (t >= off) sh[t] += u;
        __syncthreads();
    }
    int run = (t == 0) ? 0 : sh[t - 1];
#pragma unroll
    for (int i = 0; i < SCAN_E; i++) {
        if (base + i <= N) g_rowptr[base + i] = run;
        run += v[i];
    }
    if (t == SCAN_T - 1) g_bsum[b] = sh[SCAN_T - 1];
}

__global__ void __launch_bounds__(SCAN_T) scan2_kernel(int nb) {
    __shared__ int sh[SCAN_T];
    int t = threadIdx.x;
    sh[t] = (t < nb) ? g_bsum[t] : 0;
    __syncthreads();
    for (int off = 1; off < SCAN_T; off <<= 1) {
        int u = 0;
        if (t >= off) u = sh[t - off];
        __syncthreads();
        if (t >= off) sh[t] += u;
        __syncthreads();
    }
    if (t < nb) g_bsum[t] = (t == 0) ? 0 : sh[t - 1];
}

__global__ void __launch_bounds__(256) scan3_kernel(int N) {
    int i = blockIdx.x * 256 + threadIdx.x;
    if (i > N) return;
    int v = g_rowptr[i] + g_bsum[i / SCAN_B];
    g_rowptr[i] = v;
    if (i < N) g_cursor[i] = v;
}

__global__ void __launch_bounds__(256) fill_kernel(const void* __restrict__ eidx, int E) {
    int e = blockIdx.x * 256 + threadIdx.x;
    if (e >= E) return;
    int d = edge_dst(eidx, E, e);
    int s = edge_src(eidx, E, e);
    int pos = atomicAdd(&g_cursor[d], 1);
    g_adj[pos] = s;
}

// ===========================================================================
// Gather aggregation: warp per node, lane owns 4 features.
// ===========================================================================
template <int APPLY>
__global__ void __launch_bounds__(256) aggregate_kernel(const float* __restrict__ x, int N) {
    int node = (blockIdx.x * 256 + threadIdx.x) >> 5;
    int lane = threadIdx.x & 31;
    if (node >= N) return;

    const float* base = APPLY ? (const float*)g_h4 : x;
    float4 sc, sh;
    if (APPLY) {
        sc = *(const float4*)&g_sc[0][lane * 4];
        sh = *(const float4*)&g_sh[0][lane * 4];
    }

    float4 v = *(const float4*)(base + (size_t)node * 128 + lane * 4);
    float4 acc;
    if (APPLY) {
        acc.x = fmaf(v.x, sc.x, sh.x); acc.y = fmaf(v.y, sc.y, sh.y);
        acc.z = fmaf(v.z, sc.z, sh.z); acc.w = fmaf(v.w, sc.w, sh.w);
    } else {
        acc = v;
    }

    int start = g_rowptr[node];
    int end   = g_rowptr[node + 1];
    for (int j0 = start; j0 < end; j0 += 32) {
        int n = end - j0; if (n > 32) n = 32;
        int myIdx = (lane < n) ? g_adj[j0 + lane] : 0;
#pragma unroll 4
        for (int k = 0; k < n; k++) {
            int nb = __shfl_sync(0xffffffffu, myIdx, k);
            float4 w = *(const float4*)(base + (size_t)nb * 128 + lane * 4);
            if (APPLY) {
                acc.x += fmaf(w.x, sc.x, sh.x); acc.y += fmaf(w.y, sc.y, sh.y);
                acc.z += fmaf(w.z, sc.z, sh.z); acc.w += fmaf(w.w, sc.w, sh.w);
            } else {
                acc.x += w.x; acc.y += w.y; acc.z += w.z; acc.w += w.w;
            }
        }
    }
    *(float4*)((float*)g_t4 + (size_t)node * 128 + lane * 4) = acc;
}

// ===========================================================================
// bf16 split helpers
// ===========================================================================
__device__ __forceinline__ void split_pack(float v0, float v1, u32& hi, u32& lo) {
    __nv_bfloat16 h0 = __float2bfloat16(v0), h1 = __float2bfloat16(v1);
    __nv_bfloat16 l0 = __float2bfloat16(v0 - __bfloat162float(h0));
    __nv_bfloat16 l1 = __float2bfloat16(v1 - __bfloat162float(h1));
    __nv_bfloat162 hp = __halves2bfloat162(h0, h1);
    __nv_bfloat162 lp = __halves2bfloat162(l0, l1);
    hi = *(u32*)&hp; lo = *(u32*)&lp;
}

// ===========================================================================
// Prep: W^T -> mma B-fragment layout, split hi/lo.
// B fragment (m16n8k16 col-major B): element (k-pair, n) ->
//   ntile=n>>3, g=n&7, ktile=k>>4, tig=(k&7)>>1, khalf=(k>>3)&1
//   idx = ((ntile*8+ktile)*32 + g*4+tig)*2 + khalf
// ===========================================================================
__global__ void __launch_bounds__(256) prep_w_kernel(const float* __restrict__ W1,
                                                     const float* __restrict__ W2) {
    int i = blockIdx.x * 256 + threadIdx.x;     // 0..16383
    if (i >= 16384) return;
    int l = i >> 13;
    int j = i & 8191;
    int n = j >> 6;
    int k = (j & 63) * 2;
    const float* W = l ? W2 : W1;
    float v0 = W[k * 128 + n];
    float v1 = W[(k + 1) * 128 + n];
    u32 hi, lo;
    split_pack(v0, v1, hi, lo);
    int idx = ((((n >> 3) * 8) + (k >> 4)) * 32 + (n & 7) * 4 + ((k & 7) >> 1)) * 2
              + ((k >> 3) & 1);
    g_wf_hi[l][idx] = hi;
    g_wf_lo[l][idx] = lo;
}

// ===========================================================================
// mma.sync bf16 GEMM (split-3) + bias + ReLU + BN stats.
// CTA: 128 rows x 128 cols, K=128. 8 warps: wm=wid&3 (rows), wn=wid>>2 (cols).
// Fragments stored in smem in exact per-lane layout -> conflict-free LDS.
// ===========================================================================
#define SM_SSUM 0
#define SM_SSQ  512
#define SM_AH   1024
#define SM_AL   (1024 + 32768)
#define SM_BH   (1024 + 65536)
#define SM_BL   (1024 + 98304)
#define GEMM_SMEM_TOTAL (1024 + 131072)

__device__ __forceinline__ void mma_bf16(float* c, const u32* a, const u32* b) {
    asm volatile(
        "mma.sync.aligned.m16n8k16.row.col.f32.bf16.bf16.f32 "
        "{%0,%1,%2,%3}, {%4,%5,%6,%7}, {%8,%9}, {%0,%1,%2,%3};"
        : "+f"(c[0]), "+f"(c[1]), "+f"(c[2]), "+f"(c[3])
        : "r"(a[0]), "r"(a[1]), "r"(a[2]), "r"(a[3]), "r"(b[0]), "r"(b[1]));
}

__global__ void __launch_bounds__(256) gemm_tc_kernel(const float* __restrict__ bias,
                                                      int layer, int N) {
    extern __shared__ char smem[];
    u32* AH = (u32*)(smem + SM_AH);
    u32* AL = (u32*)(smem + SM_AL);
    u32* BH = (u32*)(smem + SM_BH);
    u32* BL = (u32*)(smem + SM_BL);
    float* s_sum = (float*)(smem + SM_SSUM);
    float* s_sq  = (float*)(smem + SM_SSQ);

    int tid = threadIdx.x, wid = tid >> 5, lane = tid & 31;
    int row0 = blockIdx.x * 128;
    const float* A = (const float*)g_t4;
    float* H = (float*)g_h4;

    if (tid < 128) { s_sum[tid] = 0.f; s_sq[tid] = 0.f; }

    // ---- A fragments: (r, k-pair) -> AH/AL[((mtile*8+ktile)*32+lane)*4+reg]
    for (int p = tid; p < 8192; p += 256) {
        int r = p >> 6;
        int k = (p & 63) * 2;
        int gr = row0 + r;
        float2 v = (gr < N) ? *(const float2*)(A + (size_t)gr * 128 + k)
                            : make_float2(0.f, 0.f);
        u32 hi, lo;
        split_pack(v.x, v.y, hi, lo);
        int idx = ((((r >> 4) * 8) + (k >> 4)) * 32 + (r & 7) * 4 + ((k & 7) >> 1)) * 4
                  + ((k >> 3) & 1) * 2 + ((r >> 3) & 1);
        AH[idx] = hi; AL[idx] = lo;
    }
    // ---- B fragments: bulk copy from prepped gmem
    {
        const float4* sh = (const float4*)g_wf_hi[layer];
        const float4* sl = (const float4*)g_wf_lo[layer];
        float4* dh = (float4*)BH;
        float4* dl = (float4*)BL;
        for (int p = tid; p < 2048; p += 256) { dh[p] = sh[p]; dl[p] = sl[p]; }
    }
    __syncthreads();

    // ---- Compute: warp tile 32 rows (2 mtiles) x 64 cols (8 ntiles)
    int wm = wid & 3, wn = wid >> 2;
    float acc[2][8][4];
#pragma unroll
    for (int m = 0; m < 2; m++)
#pragma unroll
        for (int n = 0; n < 8; n++)
#pragma unroll
            for (int q = 0; q < 4; q++) acc[m][n][q] = 0.f;

#pragma unroll
    for (int kt = 0; kt < 8; kt++) {
        u32 ah[2][4], al[2][4];
#pragma unroll
        for (int m = 0; m < 2; m++) {
            int base = (((wm * 2 + m) * 8 + kt) * 32 + lane) * 4;
            *(uint4*)ah[m] = *(const uint4*)(AH + base);
            *(uint4*)al[m] = *(const uint4*)(AL + base);
        }
        u32 bh[8][2], bl[8][2];
#pragma unroll
        for (int n = 0; n < 8; n++) {
            int base = (((wn * 8 + n) * 8 + kt) * 32 + lane) * 2;
            *(uint2*)bh[n] = *(const uint2*)(BH + base);
            *(uint2*)bl[n] = *(const uint2*)(BL + base);
        }
#pragma unroll
        for (int m = 0; m < 2; m++)
#pragma unroll
            for (int n = 0; n < 8; n++) {
                mma_bf16(acc[m][n], ah[m], bh[n]);
                mma_bf16(acc[m][n], ah[m], bl[n]);
                mma_bf16(acc[m][n], al[m], bh[n]);
            }
    }

    // ---- Epilogue: bias + relu + store + BN stats
    int g = lane >> 2, tig = lane & 3;
#pragma unroll
    for (int n = 0; n < 8; n++) {
        int cbase = wn * 64 + n * 8 + tig * 2;
        float2 bb = *(const float2*)(bias + cbase);
        float s0 = 0.f, s1 = 0.f, q0 = 0.f, q1 = 0.f;
#pragma unroll
        for (int m = 0; m < 2; m++) {
            int rb = row0 + (wm * 2 + m) * 16 + g;
#pragma unroll
            for (int rh = 0; rh < 2; rh++) {
                int gr = rb + rh * 8;
                float h0 = fmaxf(acc[m][n][rh * 2 + 0] + bb.x, 0.f);
                float h1 = fmaxf(acc[m][n][rh * 2 + 1] + bb.y, 0.f);
                if (gr < N) {
                    *(float2*)(H + (size_t)gr * 128 + cbase) = make_float2(h0, h1);
                    s0 += h0; s1 += h1;
                    q0 += h0 * h0; q1 += h1 * h1;
                }
            }
        }
        // reduce over the 8 row-groups (lanes with same tig)
#pragma unroll
        for (int o = 4; o < 32; o <<= 1) {
            s0 += __shfl_xor_sync(0xffffffffu, s0, o);
            s1 += __shfl_xor_sync(0xffffffffu, s1, o);
            q0 += __shfl_xor_sync(0xffffffffu, q0, o);
            q1 += __shfl_xor_sync(0xffffffffu, q1, o);
        }
        if (g == 0) {
            atomicAdd(&s_sum[cbase], s0);
            atomicAdd(&s_sum[cbase + 1], s1);
            atomicAdd(&s_sq[cbase], q0);
            atomicAdd(&s_sq[cbase + 1], q1);
        }
    }

    __syncthreads();
    if (tid < 128) {
        atomicAdd(&g_sum[layer][tid], s_sum[tid]);
        atomicAdd(&g_sq[layer][tid], s_sq[tid]);
    }
}

// ===========================================================================
// BN finalize + final apply.
// ===========================================================================
__global__ void bn_finalize_kernel(const float* __restrict__ gamma,
                                   const float* __restrict__ beta,
                                   int layer, float invN) {
    int c = threadIdx.x;
    float m = g_sum[layer][c] * invN;
    float var = g_sq[layer][c] * invN - m * m;
    float s = gamma[c] * rsqrtf(var + 1e-5f);
    g_sc[layer][c] = s;
    g_sh[layer][c] = beta[c] - m * s;
}

__global__ void __launch_bounds__(256) bn_apply_kernel(float4* __restrict__ dst,
                                                       int layer, int n4) {
    int i = blockIdx.x * 256 + threadIdx.x;
    if (i >= n4) return;
    int c = (i & 31) * 4;
    float4 v = g_h4[i];
    float4 a = *(const float4*)&g_sc[layer][c];
    float4 b = *(const float4*)&g_sh[layer][c];
    v.x = fmaf(v.x, a.x, b.x); v.y = fmaf(v.y, a.y, b.y);
    v.z = fmaf(v.z, a.z, b.z); v.w = fmaf(v.w, a.w, b.w);
    dst[i] = v;
}

// ===========================================================================
// Launch
// ===========================================================================
extern "C" void kernel_launch(void* const* d_in, const int* in_sizes, int n_in,
                              void* d_out, int out_size) {
    const float* x    = (const float*)d_in[0];
    const void*  eidx = d_in[1];
    const float* W1   = (const float*)d_in[2];
    const float* b1   = (const float*)d_in[3];
    const float* W2   = (const float*)d_in[4];
    const float* b2   = (const float*)d_in[5];
    const float* g1   = (const float*)d_in[6];
    const float* be1  = (const float*)d_in[7];
    const float* g2   = (const float*)d_in[8];
    const float* be2  = (const float*)d_in[9];

    int N = in_sizes[0] / 128;
    int E = in_sizes[1] / 2;
    int n4 = N * 32;
    int cgrid = (n4 + 255) / 256;
    int egrid = (E + 255) / 256;
    int ngrid = (N + 255) / 256;
    int agrid = (N * 32 + 255) / 256;
    int nb = (N + 1 + SCAN_B - 1) / SCAN_B;
    int gblk = (N + 127) / 128;
    float invN = 1.0f / (float)N;

    static bool attr_set = false;
    if (!attr_set) {
        cudaFuncSetAttribute(gemm_tc_kernel,
                             cudaFuncAttributeMaxDynamicSharedMemorySize, GEMM_SMEM_TOTAL);
        attr_set = true;
    }

    // ---- CSR build + weight prep ----
    detect_zero_kernel<<<1, 256>>>((const int*)eidx, E);
    zero_cnt_kernel<<<ngrid, 256>>>(N);
    hist_kernel<<<egrid, 256>>>(eidx, E);
    prep_w_kernel<<<64, 256>>>(W1, W2);
    scan1_kernel<<<nb, SCAN_T>>>(N);
    scan2_kernel<<<1, SCAN_T>>>(nb);
    scan3_kernel<<<(N + 256) / 256, 256>>>(N);
    fill_kernel<<<egrid, 256>>>(eidx, E);

    // ---- Layer 1 ----
    aggregate_kernel<0><<<agrid, 256>>>(x, N);
    gemm_tc_kernel<<<gblk, 256, GEMM_SMEM_TOTAL>>>(b1, 0, N);
    bn_finalize_kernel<<<1, 128>>>(g1, be1, 0, invN);

    // ---- Layer 2 (BN of layer 1 fused into the gather) ----
    aggregate_kernel<1><<<agrid, 256>>>(x, N);
    gemm_tc_kernel<<<gblk, 256, GEMM_SMEM_TOTAL>>>(b2, 1, N);
    bn_finalize_kernel<<<1, 128>>>(g2, be2, 1, invN);
    bn_apply_kernel<<<cgrid, 256>>>((float4*)d_out, 1, n4);
}